// round 15
// baseline (speedup 1.0000x reference)
#include <cuda_runtime.h>
#include <cuda_bf16.h>
#include <math.h>
#include <stdint.h>

// ---------------------------------------------------------------------------
// ImageCaptionModel GRU decoder. B=128,T=25,V=10000,E=512,NF=2048,H=512.
// Round 14R (resubmission; broker timeout):
//  - pre3 UN-fused from loop_kernel (r13 fusion hit 255 regs -> spills).
//    pre3_gemm standalone with the ldmatrix gemm_core (~126 regs).
//  - input layer P computed directly in fp32 inside prep_kernel (deletes
//    input_gemm launch + cnn/Win packing); launch order now puts the clean
//    loop_kernel at index 3 -> next ncu capture profiles the recurrent loop.
// Math: 3-pass bf16-split mma.m16n8k16 (AhiBhi+AhiBlo+AloBhi, fp32 acc).
// ---------------------------------------------------------------------------

namespace {
constexpr int cB = 128, cT = 25, cV = 10000, cE = 512;
constexpr int cH = 512, cMAP = 512, cTB = cB * cT;
constexpr long long LOGITS_ELEMS = (long long)cB * cT * cV;
}

// -------- scratch (__device__ globals; no allocation allowed) --------------
__device__ float d_P[cB * cMAP];
__device__ uint32_t d_XH[cTB * 512], d_XL[cTB * 512];
__device__ float d_A0u[cTB * cH], d_A0r[cTB * cH], d_A0c[cTB * cH];
__device__ uint32_t d_H1H[cTB * 256], d_H1L[cTB * 256];
__device__ float d_h0f[cB * cH], d_h1f[cB * cH];
__device__ float d_U0[cB * cH], d_U1[cB * cH];
__device__ uint32_t d_h0pH[cB * 256], d_h0pL[cB * 256];
__device__ uint32_t d_h1pH[cB * 256], d_h1pL[cB * 256];
__device__ uint32_t d_RH0H[cB * 256], d_RH0L[cB * 256];
__device__ uint32_t d_RH1H[cB * 256], d_RH1L[cB * 256];
// k-major packed weights [kp][N]
__device__ uint32_t d_Wu0xH[512 * 512], d_Wu0xL[512 * 512];
__device__ uint32_t d_Wr0xH[512 * 512], d_Wr0xL[512 * 512];
__device__ uint32_t d_Wc0xH[512 * 512], d_Wc0xL[512 * 512];
__device__ uint32_t d_WoutH[256 * 10000], d_WoutL[256 * 10000];
// n-major packed weights [n][kp]
__device__ uint32_t d_WU0hH[512 * 256], d_WU0hL[512 * 256];
__device__ uint32_t d_WR0hH[512 * 256], d_WR0hL[512 * 256];
__device__ uint32_t d_WC0rhH[512 * 256], d_WC0rhL[512 * 256];
__device__ uint32_t d_WU1H[512 * 512], d_WU1L[512 * 512];
__device__ uint32_t d_WR1H[512 * 512], d_WR1L[512 * 512];
__device__ uint32_t d_WC1H[512 * 512], d_WC1L[512 * 512];
__device__ int d_tok64;
__device__ unsigned g_cnt = 0;
__device__ volatile unsigned g_gen = 0;

// -------- helpers ----------------------------------------------------------
__device__ __forceinline__ float sigf(float x) { return 1.0f / (1.0f + __expf(-x)); }

__device__ __forceinline__ void bf16_split(float a, float b, uint32_t& hi, uint32_t& lo) {
    __nv_bfloat162 h;
    h.x = __float2bfloat16_rn(a);
    h.y = __float2bfloat16_rn(b);
    __nv_bfloat162 l;
    l.x = __float2bfloat16_rn(a - __bfloat162float(h.x));
    l.y = __float2bfloat16_rn(b - __bfloat162float(h.y));
    hi = *reinterpret_cast<uint32_t*>(&h);
    lo = *reinterpret_cast<uint32_t*>(&l);
}

__device__ __forceinline__ void mma_bf(
    float& c0, float& c1, float& c2, float& c3,
    uint32_t a0, uint32_t a1, uint32_t a2, uint32_t a3,
    uint32_t b0, uint32_t b1)
{
    asm volatile(
        "mma.sync.aligned.m16n8k16.row.col.f32.bf16.bf16.f32 "
        "{%0,%1,%2,%3}, {%4,%5,%6,%7}, {%8,%9}, {%0,%1,%2,%3};\n"
        : "+f"(c0), "+f"(c1), "+f"(c2), "+f"(c3)
        : "r"(a0), "r"(a1), "r"(a2), "r"(a3), "r"(b0), "r"(b1));
}

__device__ __forceinline__ void ldsm4(uint32_t& r0, uint32_t& r1, uint32_t& r2,
                                      uint32_t& r3, uint32_t addr) {
    asm volatile("ldmatrix.sync.aligned.m8n8.x4.shared.b16 {%0,%1,%2,%3}, [%4];"
                 : "=r"(r0), "=r"(r1), "=r"(r2), "=r"(r3) : "r"(addr));
}

__device__ __forceinline__ uint32_t smem_u32(const void* p) {
    uint32_t a;
    asm("{ .reg .u64 t; cvta.to.shared.u64 t, %1; cvt.u32.u64 %0, t; }" : "=r"(a) : "l"(p));
    return a;
}

// swizzled byte offset of 16B-unit (row r in [0,128), half h in {0,1}) within
// a 4KB operand array. Conflict-free for LDSM 8-row reads.
__device__ __forceinline__ uint32_t sw_off(int r, int h) {
    return (uint32_t)(((r >> 2) << 7) + (((((r & 3) << 1) + h) ^ ((r >> 2) & 7)) << 4));
}

// ---------------------------------------------------------------------------
// prep_kernel: block 0 = token dtype detect; blocks 1.. flat work list:
//   init(65536) | P=cnn@Win fp32 (65536) | W*0x(3x262144) | Wout(2560000) |
//   W*h n-major (3x131072) | W*1 n-major (3x262144)     total 4657152 items
// ---------------------------------------------------------------------------
__global__ void prep_kernel(const long long* __restrict__ t64,
    const float* __restrict__ cnn, const float* __restrict__ Win,
    const float* __restrict__ Wout,
    const float* __restrict__ Wu0, const float* __restrict__ Wr0,
    const float* __restrict__ Wc0,
    const float* __restrict__ Wu1, const float* __restrict__ Wr1,
    const float* __restrict__ Wc1)
{
    const int tid = threadIdx.x;
    if (blockIdx.x == 0) {
        __shared__ int bad;
        if (tid == 0) bad = 0;
        __syncthreads();
        for (int i = tid; i < cTB / 2; i += 256) {
            long long v = t64[i];
            if (v < 0 || v >= (long long)cV) bad = 1;
        }
        __syncthreads();
        if (tid == 0) d_tok64 = (bad == 0) ? 1 : 0;
        return;
    }
    long long idx = (long long)(blockIdx.x - 1) * 256 + tid;
    if (idx < 65536) {                      // init h (NOT d_P: written by P seg)
        int i = (int)idx;
        d_h0f[i] = 0.f; d_h1f[i] = 0.f;
        if (i < 32768) {
            d_h0pH[i] = 0u; d_h0pL[i] = 0u;
            d_h1pH[i] = 0u; d_h1pL[i] = 0u;
        }
        return;
    }
    idx -= 65536;
    if (idx < 65536) {                      // P[m][n] = cnn[m,:] @ Win[:,n] fp32
        int m = (int)(idx >> 9), n = (int)(idx & 511);
        const float* a = cnn + (long long)m * 2048;
        float s = 0.f;
        for (int k = 0; k < 2048; k += 4) {
            float4 av = *(const float4*)(a + k);
            s += av.x * Win[(long long)k * 512 + n];
            s += av.y * Win[(long long)(k + 1) * 512 + n];
            s += av.z * Win[(long long)(k + 2) * 512 + n];
            s += av.w * Win[(long long)(k + 3) * 512 + n];
        }
        d_P[idx] = s;
        return;
    }
    idx -= 65536;
    if (idx < 786432) {                     // Wu0x/Wr0x/Wc0x k-major [512][512]
        int w = (int)(idx >> 18);
        long long r = idx & 262143;
        const float* s = (w == 0) ? Wu0 : ((w == 1) ? Wr0 : (Wc0 + 512 * 512));
        uint32_t* oh = (w == 0) ? d_Wu0xH : ((w == 1) ? d_Wr0xH : d_Wc0xH);
        uint32_t* ol = (w == 0) ? d_Wu0xL : ((w == 1) ? d_Wr0xL : d_Wc0xL);
        int kp = (int)(r >> 9), n = (int)(r & 511);
        uint32_t h, l;
        bf16_split(s[(2 * kp) * 512 + n], s[(2 * kp + 1) * 512 + n], h, l);
        oh[r] = h; ol[r] = l;
        return;
    }
    idx -= 786432;
    if (idx < 2560000) {                    // Wout k-major [256][10000]
        int kp = (int)(idx / 10000);
        int n = (int)(idx - (long long)kp * 10000);
        uint32_t h, l;
        bf16_split(Wout[(long long)(2 * kp) * 10000 + n],
                   Wout[(long long)(2 * kp + 1) * 10000 + n], h, l);
        d_WoutH[idx] = h; d_WoutL[idx] = l;
        return;
    }
    idx -= 2560000;
    if (idx < 393216) {                     // WU0h/WR0h/WC0rh n-major [512][256]
        int w = (int)(idx >> 17);
        long long r = idx & 131071;
        const float* s = (w == 0) ? (Wu0 + 1024 * 512) : ((w == 1) ? (Wr0 + 1024 * 512) : Wc0);
        uint32_t* oh = (w == 0) ? d_WU0hH : ((w == 1) ? d_WR0hH : d_WC0rhH);
        uint32_t* ol = (w == 0) ? d_WU0hL : ((w == 1) ? d_WR0hL : d_WC0rhL);
        int n = (int)(r >> 8), kp = (int)(r & 255);
        uint32_t h, l;
        bf16_split(s[(2 * kp) * 512 + n], s[(2 * kp + 1) * 512 + n], h, l);
        oh[r] = h; ol[r] = l;
        return;
    }
    idx -= 393216;
    if (idx < 786432) {                     // WU1/WR1/WC1 n-major [512][512]
        int w = (int)(idx >> 18);
        long long r = idx & 262143;
        const float* s = (w == 0) ? Wu1 : ((w == 1) ? Wr1 : Wc1);
        uint32_t* oh = (w == 0) ? d_WU1H : ((w == 1) ? d_WR1H : d_WC1H);
        uint32_t* ol = (w == 0) ? d_WU1L : ((w == 1) ? d_WR1L : d_WC1L);
        int n = (int)(r >> 9), kp = (int)(r & 511);
        uint32_t h, l;
        bf16_split(s[(2 * kp) * 512 + n], s[(2 * kp + 1) * 512 + n], h, l);
        oh[r] = h; ol[r] = l;
    }
}

__global__ void gather_pack_kernel(const long long* __restrict__ tok64,
                                   const int* __restrict__ tok32,
                                   const float* __restrict__ emb,
                                   const float* __restrict__ bin_) {
    int idx = blockIdx.x * blockDim.x + threadIdx.x;
    if (idx >= cTB * 512) return;
    int m = idx >> 9, kp = idx & 511;
    int tt = m / cB, b = m % cB;
    float2 v;
    if (kp < 256) {
        int tok = d_tok64 ? (int)tok64[b * cT + tt] : tok32[b * cT + tt];
        v = *(const float2*)(emb + (long long)tok * cE + 2 * kp);
    } else {
        int k2 = kp - 256;
        float2 raw = *(const float2*)(d_P + b * cMAP + 2 * k2);
        v.x = raw.x + bin_[2 * k2];
        v.y = raw.y + bin_[2 * k2 + 1];
        v.x = v.x > 0.f ? v.x : 0.01f * v.x;
        v.y = v.y > 0.f ? v.y : 0.01f * v.y;
    }
    uint32_t h, l;
    bf16_split(v.x, v.y, h, l);
    d_XH[idx] = h; d_XL[idx] = l;
}

// ---------------------------------------------------------------------------
// gemm_core (ldmatrix edition). Pool per buffer (16KB):
//   [0,4K) A-hi  [4K,8K) A-lo  [8K,12K) B-hi  [12K,16K) B-lo
// 128 rows x 32B per operand, xor-swizzled. Double buffered: 32KB.
// ---------------------------------------------------------------------------
__device__ __forceinline__ void gemm_core(
    const uint32_t* __restrict__ AH, const uint32_t* __restrict__ AL, int as,
    const uint32_t* __restrict__ BH, const uint32_t* __restrict__ BL,
    const float* __restrict__ bias, float* __restrict__ C,
    int N, int K, int act, int remap, int m0, int n0, char* pool)
{
    const uint32_t sbase = smem_u32(pool);
    const int tid = threadIdx.x;
    const int wid = tid >> 5, lane = tid & 31;
    const int grp = lane >> 2, tig = lane & 3;
    const int wm = (wid >> 1) * 32, wn = (wid & 1) * 64;
    const int ar = tid >> 2, kb = (tid & 3) << 1;
    const int kp = (tid >> 4) & 7;
    const int bn = ((tid & 15) << 2) + ((tid >> 7) << 6);
    const int NC = K >> 4;

    const uint32_t oA0 = sw_off(ar, kb >> 2) + ((kb & 3) << 2);
    const uint32_t oA1 = sw_off(ar + 64, kb >> 2) + ((kb & 3) << 2);
    uint32_t oB[4];
#pragma unroll
    for (int j = 0; j < 4; j++) oB[j] = sw_off(bn + j, kp >> 2) + ((kp & 3) << 2);

    const int rA = (lane & 15);
    const uint32_t hA = (uint32_t)(lane >> 4);
    const int rB = (lane & 7) + ((lane >> 4) << 3);
    const uint32_t hB = (uint32_t)((lane >> 3) & 1);

    float acc[2][8][4] = {};
    uint2 a0h, a0l, a1h, a1l;
    uint4 bh, bl;

    {
        const uint32_t* pa = AH + (long long)(m0 + ar) * as + kb;
        const uint32_t* pl = AL + (long long)(m0 + ar) * as + kb;
        a0h = *(const uint2*)pa; a1h = *(const uint2*)(pa + (long long)64 * as);
        a0l = *(const uint2*)pl; a1l = *(const uint2*)(pl + (long long)64 * as);
        int n = n0 + bn;
        if (n < N) {
            bh = *(const uint4*)(BH + (long long)kp * N + n);
            bl = *(const uint4*)(BL + (long long)kp * N + n);
        } else { bh = make_uint4(0, 0, 0, 0); bl = bh; }
    }
    {
        char* pA = pool;
        char* pB = pool + 8192;
        *(uint2*)(pA + oA0) = a0h; *(uint2*)(pA + oA1) = a1h;
        *(uint2*)(pA + 4096 + oA0) = a0l; *(uint2*)(pA + 4096 + oA1) = a1l;
        *(uint32_t*)(pB + oB[0]) = bh.x; *(uint32_t*)(pB + oB[1]) = bh.y;
        *(uint32_t*)(pB + oB[2]) = bh.z; *(uint32_t*)(pB + oB[3]) = bh.w;
        *(uint32_t*)(pB + 4096 + oB[0]) = bl.x; *(uint32_t*)(pB + 4096 + oB[1]) = bl.y;
        *(uint32_t*)(pB + 4096 + oB[2]) = bl.z; *(uint32_t*)(pB + 4096 + oB[3]) = bl.w;
    }
    __syncthreads();

    for (int c = 0; c < NC; c++) {
        const int buf = c & 1;
        const int kn = (c + 1) << 4;
        if (kn < K) {
            const uint32_t* pa = AH + (long long)(m0 + ar) * as + (kn >> 1) + kb;
            const uint32_t* pl = AL + (long long)(m0 + ar) * as + (kn >> 1) + kb;
            a0h = *(const uint2*)pa; a1h = *(const uint2*)(pa + (long long)64 * as);
            a0l = *(const uint2*)pl; a1l = *(const uint2*)(pl + (long long)64 * as);
            int n = n0 + bn;
            if (n < N) {
                bh = *(const uint4*)(BH + (long long)((kn >> 1) + kp) * N + n);
                bl = *(const uint4*)(BL + (long long)((kn >> 1) + kp) * N + n);
            } else { bh = make_uint4(0, 0, 0, 0); bl = bh; }
        }

        const uint32_t base = sbase + (uint32_t)buf * 16384;
        uint32_t aHf[2][4], aLf[2][4];
#pragma unroll
        for (int mf = 0; mf < 2; mf++) {
            uint32_t addr = base + sw_off(wm + mf * 16 + rA, hA);
            ldsm4(aHf[mf][0], aHf[mf][1], aHf[mf][2], aHf[mf][3], addr);
            ldsm4(aLf[mf][0], aLf[mf][1], aLf[mf][2], aLf[mf][3], addr + 4096);
        }
#pragma unroll
        for (int nfp = 0; nfp < 4; nfp++) {
            uint32_t addrB = base + 8192 + sw_off(wn + nfp * 16 + rB, hB);
            uint32_t bH0, bH1, bH2, bH3, bL0, bL1, bL2, bL3;
            ldsm4(bH0, bH1, bH2, bH3, addrB);
            ldsm4(bL0, bL1, bL2, bL3, addrB + 4096);
#pragma unroll
            for (int mf = 0; mf < 2; mf++) {
                float* c0 = acc[mf][nfp * 2];
                float* c1 = acc[mf][nfp * 2 + 1];
                mma_bf(c0[0], c0[1], c0[2], c0[3],
                       aHf[mf][0], aHf[mf][1], aHf[mf][2], aHf[mf][3], bH0, bH1);
                mma_bf(c0[0], c0[1], c0[2], c0[3],
                       aHf[mf][0], aHf[mf][1], aHf[mf][2], aHf[mf][3], bL0, bL1);
                mma_bf(c0[0], c0[1], c0[2], c0[3],
                       aLf[mf][0], aLf[mf][1], aLf[mf][2], aLf[mf][3], bH0, bH1);
                mma_bf(c1[0], c1[1], c1[2], c1[3],
                       aHf[mf][0], aHf[mf][1], aHf[mf][2], aHf[mf][3], bH2, bH3);
                mma_bf(c1[0], c1[1], c1[2], c1[3],
                       aHf[mf][0], aHf[mf][1], aHf[mf][2], aHf[mf][3], bL2, bL3);
                mma_bf(c1[0], c1[1], c1[2], c1[3],
                       aLf[mf][0], aLf[mf][1], aLf[mf][2], aLf[mf][3], bH2, bH3);
            }
        }

        if (kn < K) {
            char* pA = pool + (buf ^ 1) * 16384;
            char* pB = pA + 8192;
            *(uint2*)(pA + oA0) = a0h; *(uint2*)(pA + oA1) = a1h;
            *(uint2*)(pA + 4096 + oA0) = a0l; *(uint2*)(pA + 4096 + oA1) = a1l;
            *(uint32_t*)(pB + oB[0]) = bh.x; *(uint32_t*)(pB + oB[1]) = bh.y;
            *(uint32_t*)(pB + oB[2]) = bh.z; *(uint32_t*)(pB + oB[3]) = bh.w;
            *(uint32_t*)(pB + 4096 + oB[0]) = bl.x; *(uint32_t*)(pB + 4096 + oB[1]) = bl.y;
            *(uint32_t*)(pB + 4096 + oB[2]) = bl.z; *(uint32_t*)(pB + 4096 + oB[3]) = bl.w;
        }
        __syncthreads();
    }

#pragma unroll
    for (int mf = 0; mf < 2; mf++) {
        int r0 = m0 + wm + mf * 16 + grp;
        int r1 = r0 + 8;
        long long base0, base1;
        if (remap) {
            int b0r = r0 & (cB - 1), t0 = r0 >> 7;
            int b1r = r1 & (cB - 1), t1 = r1 >> 7;
            base0 = (long long)(b0r * cT + t0) * N;
            base1 = (long long)(b1r * cT + t1) * N;
        } else {
            base0 = (long long)r0 * N;
            base1 = (long long)r1 * N;
        }
#pragma unroll
        for (int nf = 0; nf < 8; nf++) {
            int n = n0 + wn + nf * 8 + tig * 2;
            if (n < N) {
                float o00 = acc[mf][nf][0] + bias[n];
                float o01 = acc[mf][nf][1] + bias[n + 1];
                float o10 = acc[mf][nf][2] + bias[n];
                float o11 = acc[mf][nf][3] + bias[n + 1];
                if (act == 1) {
                    o00 = o00 > 0.f ? o00 : 0.01f * o00;
                    o01 = o01 > 0.f ? o01 : 0.01f * o01;
                    o10 = o10 > 0.f ? o10 : 0.01f * o10;
                    o11 = o11 > 0.f ? o11 : 0.01f * o11;
                }
                C[base0 + n] = o00; C[base0 + n + 1] = o01;
                C[base1 + n] = o10; C[base1 + n + 1] = o11;
            }
        }
    }
}

// wrappers -------------------------------------------------------------------
__global__ __launch_bounds__(256) void pre3_gemm(
    const float* __restrict__ bu0, const float* __restrict__ br0,
    const float* __restrict__ bc0) {
    __shared__ __align__(16) char pool[32768];
    int z = blockIdx.z;
    const uint32_t* BH = (z == 0) ? d_Wu0xH : ((z == 1) ? d_Wr0xH : d_Wc0xH);
    const uint32_t* BL = (z == 0) ? d_Wu0xL : ((z == 1) ? d_Wr0xL : d_Wc0xL);
    const float* bias = (z == 0) ? bu0 : ((z == 1) ? br0 : bc0);
    float* C = (z == 0) ? d_A0u : ((z == 1) ? d_A0r : d_A0c);
    gemm_core(d_XH, d_XL, 512, BH, BL, bias, C, 512, 1024, 0, 0,
              blockIdx.y * 128, blockIdx.x * 128, pool);
}

__global__ __launch_bounds__(256) void logits_gemm(
    const float* __restrict__ bout, float* __restrict__ out) {
    __shared__ __align__(16) char pool[32768];
    gemm_core(d_H1H, d_H1L, 256, d_WoutH, d_WoutL, bout, out, cV, 512, 0, 1,
              blockIdx.y * 128, blockIdx.x * 128, pool);
}

// ---------------------------------------------------------------------------
// Persistent recurrent loop (byte-identical phases to round 7/9 passing code).
// ---------------------------------------------------------------------------
__device__ __forceinline__ void grid_bar() {
    __syncthreads();
    if (threadIdx.x == 0) {
        unsigned gen = g_gen;
        __threadfence();
        if (atomicAdd(&g_cnt, 1u) == 127u) {
            atomicExch(&g_cnt, 0u);
            __threadfence();
            g_gen = gen + 1;
        } else {
            while (g_gen == gen) { }
        }
        __threadfence();
    }
    __syncthreads();
}

template <int NITER, int MF>
__device__ __forceinline__ void tile_gemm(
    const uint32_t* __restrict__ AH, const uint32_t* __restrict__ AL, int kpa0,
    const uint32_t* __restrict__ BH, const uint32_t* __restrict__ BL, int bs, int kpb0,
    int m0, int n0, int grp, int tig, float (&acc)[MF][4][4])
{
#pragma unroll
    for (int it = 0; it < NITER; it++) {
        const int kpA = kpa0 + it * 8, kpB = kpb0 + it * 8;
        uint32_t aH[MF][4], aL[MF][4];
#pragma unroll
        for (int mf = 0; mf < MF; mf++) {
            const int r = (m0 + mf * 16 + grp) * 256 + kpA;
            aH[mf][0] = __ldcg(AH + r + tig);        aH[mf][1] = __ldcg(AH + r + 2048 + tig);
            aH[mf][2] = __ldcg(AH + r + tig + 4);    aH[mf][3] = __ldcg(AH + r + 2048 + tig + 4);
            aL[mf][0] = __ldcg(AL + r + tig);        aL[mf][1] = __ldcg(AL + r + 2048 + tig);
            aL[mf][2] = __ldcg(AL + r + tig + 4);    aL[mf][3] = __ldcg(AL + r + 2048 + tig + 4);
        }
#pragma unroll
        for (int nf = 0; nf < 4; nf++) {
            const int nb = (n0 + nf * 8 + grp) * bs + kpB;
            uint32_t b0H = __ldg(BH + nb + tig), b1H = __ldg(BH + nb + tig + 4);
            uint32_t b0L = __ldg(BL + nb + tig), b1L = __ldg(BL + nb + tig + 4);
#pragma unroll
            for (int mf = 0; mf < MF; mf++) {
                float* c = acc[mf][nf];
                mma_bf(c[0], c[1], c[2], c[3],
                       aH[mf][0], aH[mf][1], aH[mf][2], aH[mf][3], b0H, b1H);
                mma_bf(c[0], c[1], c[2], c[3],
                       aH[mf][0], aH[mf][1], aH[mf][2], aH[mf][3], b0L, b1L);
                mma_bf(c[0], c[1], c[2], c[3],
                       aL[mf][0], aL[mf][1], aL[mf][2], aL[mf][3], b0H, b1H);
            }
        }
    }
}

template <int MF>
__device__ __forceinline__ void store_red(float (*red)[1024], float (&acc)[MF][4][4],
                                          int wid, int grp, int tig) {
#pragma unroll
    for (int mf = 0; mf < MF; mf++)
#pragma unroll
        for (int nf = 0; nf < 4; nf++) {
            int c = nf * 8 + tig * 2, r = mf * 16 + grp;
            red[wid][r * 32 + c] = acc[mf][nf][0];
            red[wid][r * 32 + c + 1] = acc[mf][nf][1];
            red[wid][(r + 8) * 32 + c] = acc[mf][nf][2];
            red[wid][(r + 8) * 32 + c + 1] = acc[mf][nf][3];
        }
}

__device__ __forceinline__ float4 sum_red4(float (*red)[1024], int e0) {
    float4 s = make_float4(0, 0, 0, 0);
#pragma unroll
    for (int w = 0; w < 8; w++) {
        float4 r = *(float4*)&red[w][e0];
        s.x += r.x; s.y += r.y; s.z += r.z; s.w += r.w;
    }
    return s;
}

__device__ __forceinline__ float2 sum_red2(float (*red)[1024], int e0) {
    float2 s = make_float2(0, 0);
#pragma unroll
    for (int w = 0; w < 8; w++) {
        float2 r = *(float2*)&red[w][e0];
        s.x += r.x; s.y += r.y;
    }
    return s;
}

__global__ __launch_bounds__(256) void loop_kernel(
    const float* __restrict__ bu1, const float* __restrict__ br1,
    const float* __restrict__ bc1)
{
    __shared__ float red[8][1024];
    const int tid = threadIdx.x, wid = tid >> 5, lane = tid & 31;
    const int grp = lane >> 2, tig = lane & 3;
    const int blk = blockIdx.x;

    for (int t = 0; t < cT; t++) {
        // ---- phase A: u0 (blk<64) / r0 (blk>=64), 32x32 tiles, K=512 ----
        {
            int gate = blk >> 6, tile = blk & 63;
            int m0 = (tile & 3) * 32, n0 = (tile >> 2) * 32;
            float acc[2][4][4] = {};
            tile_gemm<4, 2>(d_h0pH, d_h0pL, wid * 32,
                            gate ? d_WR0hH : d_WU0hH, gate ? d_WR0hL : d_WU0hL,
                            256, wid * 32, m0, n0, grp, tig, acc);
            store_red<2>(red, acc, wid, grp, tig);
            __syncthreads();
            const float* A0 = (gate ? d_A0r : d_A0u) + t * cB * cH;
            int e0 = tid * 4;
            float4 s = sum_red4(red, e0);
            int m = m0 + (e0 >> 5), n = n0 + (e0 & 31), o = m * cH + n;
            float4 a = *(const float4*)(A0 + o);
            if (gate == 0) {
                d_U0[o] = sigf(a.x + s.x);     d_U0[o + 1] = sigf(a.y + s.y);
                d_U0[o + 2] = sigf(a.z + s.z); d_U0[o + 3] = sigf(a.w + s.w);
            } else {
                float r0 = sigf(a.x + s.x) * __ldcg(d_h0f + o);
                float r1 = sigf(a.y + s.y) * __ldcg(d_h0f + o + 1);
                float r2 = sigf(a.z + s.z) * __ldcg(d_h0f + o + 2);
                float r3 = sigf(a.w + s.w) * __ldcg(d_h0f + o + 3);
                uint32_t h, l;
                int kp = m * 256 + (n >> 1);
                bf16_split(r0, r1, h, l); d_RH0H[kp] = h;     d_RH0L[kp] = l;
                bf16_split(r2, r3, h, l); d_RH0H[kp + 1] = h; d_RH0L[kp + 1] = l;
            }
        }
        grid_bar();
        // ---- phase B: c0, 16x32 tiles, K=512, in-place h0 update ----
        {
            int m0 = (blk & 7) * 16, n0 = (blk >> 3) * 32;
            float acc[1][4][4] = {};
            tile_gemm<4, 1>(d_RH0H, d_RH0L, wid * 32,
                            d_WC0rhH, d_WC0rhL, 256, wid * 32, m0, n0, grp, tig, acc);
            store_red<1>(red, acc, wid, grp, tig);
            __syncthreads();
            const float* A0 = d_A0c + t * cB * cH;
            int e0 = tid * 2;
            float2 s = sum_red2(red, e0);
            int m = m0 + (e0 >> 5), n = n0 + (e0 & 31), o = m * cH + n;
            float v0 = A0[o] + s.x, v1 = A0[o + 1] + s.y;
            float u0 = __ldcg(d_U0 + o), u1 = __ldcg(d_U0 + o + 1);
            float p0 = __ldcg(d_h0f + o), p1 = __ldcg(d_h0f + o + 1);
            float n0v = u0 * p0 + (1.f - u0) * tanhf(v0);
            float n1v = u1 * p1 + (1.f - u1) * tanhf(v1);
            d_h0f[o] = n0v; d_h0f[o + 1] = n1v;
            uint32_t h, l;
            bf16_split(n0v, n1v, h, l);
            int kp = m * 256 + (n >> 1);
            d_h0pH[kp] = h; d_h0pL[kp] = l;
        }
        grid_bar();
        // ---- phase C: u1 / r1, 32x32 tiles, K=1024 ([h0,h1]) ----
        {
            int gate = blk >> 6, tile = blk & 63;
            int m0 = (tile & 3) * 32, n0 = (tile >> 2) * 32;
            float acc[2][4][4] = {};
            tile_gemm<8, 2>((wid < 4) ? d_h0pH : d_h1pH, (wid < 4) ? d_h0pL : d_h1pL,
                            (wid & 3) * 64,
                            gate ? d_WR1H : d_WU1H, gate ? d_WR1L : d_WU1L,
                            512, wid * 64, m0, n0, grp, tig, acc);
            store_red<2>(red, acc, wid, grp, tig);
            __syncthreads();
            const float* bb = gate ? br1 : bu1;
            int e0 = tid * 4;
            float4 s = sum_red4(red, e0);
            int m = m0 + (e0 >> 5), n = n0 + (e0 & 31), o = m * cH + n;
            float4 b = *(const float4*)(bb + n);
            if (gate == 0) {
                d_U1[o] = sigf(b.x + s.x);     d_U1[o + 1] = sigf(b.y + s.y);
                d_U1[o + 2] = sigf(b.z + s.z); d_U1[o + 3] = sigf(b.w + s.w);
            } else {
                float r0 = sigf(b.x + s.x) * __ldcg(d_h1f + o);
                float r1 = sigf(b.y + s.y) * __ldcg(d_h1f + o + 1);
                float r2 = sigf(b.z + s.z) * __ldcg(d_h1f + o + 2);
                float r3 = sigf(b.w + s.w) * __ldcg(d_h1f + o + 3);
                uint32_t h, l;
                int kp = m * 256 + (n >> 1);
                bf16_split(r0, r1, h, l); d_RH1H[kp] = h;     d_RH1L[kp] = l;
                bf16_split(r2, r3, h, l); d_RH1H[kp + 1] = h; d_RH1L[kp + 1] = l;
            }
        }
        grid_bar();
        // ---- phase D: c1, 16x32 tiles, K=1024 ([RH1,h0]); no barrier after ----
        {
            int m0 = (blk & 7) * 16, n0 = (blk >> 3) * 32;
            float acc[1][4][4] = {};
            tile_gemm<8, 1>((wid < 4) ? d_RH1H : d_h0pH, (wid < 4) ? d_RH1L : d_h0pL,
                            (wid & 3) * 64,
                            d_WC1H, d_WC1L, 512, wid * 64, m0, n0, grp, tig, acc);
            store_red<1>(red, acc, wid, grp, tig);
            __syncthreads();
            int e0 = tid * 2;
            float2 s = sum_red2(red, e0);
            int m = m0 + (e0 >> 5), n = n0 + (e0 & 31), o = m * cH + n;
            float v0 = bc1[n] + s.x, v1 = bc1[n + 1] + s.y;
            float u0 = __ldcg(d_U1 + o), u1 = __ldcg(d_U1 + o + 1);
            float p0 = __ldcg(d_h1f + o), p1 = __ldcg(d_h1f + o + 1);
            float n0v = u0 * p0 + (1.f - u0) * tanhf(v0);
            float n1v = u1 * p1 + (1.f - u1) * tanhf(v1);
            d_h1f[o] = n0v; d_h1f[o + 1] = n1v;
            uint32_t h, l;
            bf16_split(n0v, n1v, h, l);
            int kp = m * 256 + (n >> 1);
            d_h1pH[kp] = h; d_h1pL[kp] = l;
            long long hp = (long long)(t * cB + m) * 256 + (n >> 1);
            d_H1H[hp] = h; d_H1L[hp] = l;
            __syncthreads();
        }
    }
}

__global__ void hidden_out_kernel(float* __restrict__ out) {
    int i = blockIdx.x * blockDim.x + threadIdx.x;
    if (i < cB * cH) {
        out[LOGITS_ELEMS + i] = d_h0f[i];
        out[LOGITS_ELEMS + cB * cH + i] = d_h1f[i];
    }
}

// ---------------------------------------------------------------------------
extern "C" void kernel_launch(void* const* d_in, const int* in_sizes, int n_in,
                              void* d_out, int out_size) {
    const long long* tok64 = (const long long*)d_in[0];
    const int*       tok32 = (const int*)d_in[0];
    const float* cnn  = (const float*)d_in[1];
    const float* emb  = (const float*)d_in[2];
    const float* Win  = (const float*)d_in[3];
    const float* bin_ = (const float*)d_in[4];
    const float* Wout = (const float*)d_in[5];
    const float* bout = (const float*)d_in[6];
    const float* Wu0  = (const float*)d_in[7];
    const float* bu0  = (const float*)d_in[8];
    const float* Wr0  = (const float*)d_in[9];
    const float* br0  = (const float*)d_in[10];
    const float* Wc0  = (const float*)d_in[11];
    const float* bc0  = (const float*)d_in[12];
    const float* Wu1  = (const float*)d_in[13];
    const float* bu1  = (const float*)d_in[14];
    const float* Wr1  = (const float*)d_in[15];
    const float* br1  = (const float*)d_in[16];
    const float* Wc1  = (const float*)d_in[17];
    const float* bc1  = (const float*)d_in[18];
    float* out = (float*)d_out;

    // launch 0: fused prep (detect + init + fp32 P + all packing); 4657152 items
    prep_kernel<<<18193, 256>>>(tok64, cnn, Win, Wout, Wu0, Wr0, Wc0, Wu1, Wr1, Wc1);
    // launch 1: gather + bias/leaky on P + pack X
    gather_pack_kernel<<<(cTB * 512 + 255) / 256, 256>>>(tok64, tok32, emb, bin_);
    // launch 2: precompute A0u/A0r/A0c = X @ Wx + b (ldmatrix engine)
    pre3_gemm<<<dim3(4, 25, 3), 256>>>(bu0, br0, bc0);
    // launch 3 (ncu-profiled): persistent recurrent loop (all 25 steps)
    loop_kernel<<<128, 256>>>(bu1, br1, bc1);
    // launch 4: logits = H1 @ Wout + bout -> [B,T,V]
    logits_gemm<<<dim3((cV + 127) / 128, 25), 256>>>(bout, out);
    // launch 5: hidden state outputs
    hidden_out_kernel<<<(cB * cH + 255) / 256, 256>>>(out);
}

// round 17
// speedup vs baseline: 1.0035x; 1.0035x over previous
#include <cuda_runtime.h>
#include <cuda_bf16.h>
#include <math.h>
#include <stdint.h>

// ---------------------------------------------------------------------------
// ImageCaptionModel GRU decoder. B=128,T=25,V=10000,E=512,NF=2048,H=512.
// Round 16R (resubmission; broker timeout):
//  - MEASURED defect: loop_kernel regs=255 (spills) from fully-unrolled
//    tile_gemm load pipelining; loop = 884 us (63% of runtime), tensor 8.4%.
//  - FIX: explicit 2-stage register double-buffer in tile_gemm. Live loads
//    bounded to 2 iterations (~64 regs) -> ~150 total, no spills, MLP kept.
//  All other code byte-identical to the round 14/15 passing kernel.
// Math: 3-pass bf16-split mma.m16n8k16 (AhiBhi+AhiBlo+AloBhi, fp32 acc).
// ---------------------------------------------------------------------------

namespace {
constexpr int cB = 128, cT = 25, cV = 10000, cE = 512;
constexpr int cH = 512, cMAP = 512, cTB = cB * cT;
constexpr long long LOGITS_ELEMS = (long long)cB * cT * cV;
}

// -------- scratch (__device__ globals; no allocation allowed) --------------
__device__ float d_P[cB * cMAP];
__device__ uint32_t d_XH[cTB * 512], d_XL[cTB * 512];
__device__ float d_A0u[cTB * cH], d_A0r[cTB * cH], d_A0c[cTB * cH];
__device__ uint32_t d_H1H[cTB * 256], d_H1L[cTB * 256];
__device__ float d_h0f[cB * cH], d_h1f[cB * cH];
__device__ float d_U0[cB * cH], d_U1[cB * cH];
__device__ uint32_t d_h0pH[cB * 256], d_h0pL[cB * 256];
__device__ uint32_t d_h1pH[cB * 256], d_h1pL[cB * 256];
__device__ uint32_t d_RH0H[cB * 256], d_RH0L[cB * 256];
__device__ uint32_t d_RH1H[cB * 256], d_RH1L[cB * 256];
// k-major packed weights [kp][N]
__device__ uint32_t d_Wu0xH[512 * 512], d_Wu0xL[512 * 512];
__device__ uint32_t d_Wr0xH[512 * 512], d_Wr0xL[512 * 512];
__device__ uint32_t d_Wc0xH[512 * 512], d_Wc0xL[512 * 512];
__device__ uint32_t d_WoutH[256 * 10000], d_WoutL[256 * 10000];
// n-major packed weights [n][kp]
__device__ uint32_t d_WU0hH[512 * 256], d_WU0hL[512 * 256];
__device__ uint32_t d_WR0hH[512 * 256], d_WR0hL[512 * 256];
__device__ uint32_t d_WC0rhH[512 * 256], d_WC0rhL[512 * 256];
__device__ uint32_t d_WU1H[512 * 512], d_WU1L[512 * 512];
__device__ uint32_t d_WR1H[512 * 512], d_WR1L[512 * 512];
__device__ uint32_t d_WC1H[512 * 512], d_WC1L[512 * 512];
__device__ int d_tok64;
__device__ unsigned g_cnt = 0;
__device__ volatile unsigned g_gen = 0;

// -------- helpers ----------------------------------------------------------
__device__ __forceinline__ float sigf(float x) { return 1.0f / (1.0f + __expf(-x)); }

__device__ __forceinline__ void bf16_split(float a, float b, uint32_t& hi, uint32_t& lo) {
    __nv_bfloat162 h;
    h.x = __float2bfloat16_rn(a);
    h.y = __float2bfloat16_rn(b);
    __nv_bfloat162 l;
    l.x = __float2bfloat16_rn(a - __bfloat162float(h.x));
    l.y = __float2bfloat16_rn(b - __bfloat162float(h.y));
    hi = *reinterpret_cast<uint32_t*>(&h);
    lo = *reinterpret_cast<uint32_t*>(&l);
}

__device__ __forceinline__ void mma_bf(
    float& c0, float& c1, float& c2, float& c3,
    uint32_t a0, uint32_t a1, uint32_t a2, uint32_t a3,
    uint32_t b0, uint32_t b1)
{
    asm volatile(
        "mma.sync.aligned.m16n8k16.row.col.f32.bf16.bf16.f32 "
        "{%0,%1,%2,%3}, {%4,%5,%6,%7}, {%8,%9}, {%0,%1,%2,%3};\n"
        : "+f"(c0), "+f"(c1), "+f"(c2), "+f"(c3)
        : "r"(a0), "r"(a1), "r"(a2), "r"(a3), "r"(b0), "r"(b1));
}

__device__ __forceinline__ void ldsm4(uint32_t& r0, uint32_t& r1, uint32_t& r2,
                                      uint32_t& r3, uint32_t addr) {
    asm volatile("ldmatrix.sync.aligned.m8n8.x4.shared.b16 {%0,%1,%2,%3}, [%4];"
                 : "=r"(r0), "=r"(r1), "=r"(r2), "=r"(r3) : "r"(addr));
}

__device__ __forceinline__ uint32_t smem_u32(const void* p) {
    uint32_t a;
    asm("{ .reg .u64 t; cvta.to.shared.u64 t, %1; cvt.u32.u64 %0, t; }" : "=r"(a) : "l"(p));
    return a;
}

// swizzled byte offset of 16B-unit (row r in [0,128), half h in {0,1}) within
// a 4KB operand array. Conflict-free for LDSM 8-row reads.
__device__ __forceinline__ uint32_t sw_off(int r, int h) {
    return (uint32_t)(((r >> 2) << 7) + (((((r & 3) << 1) + h) ^ ((r >> 2) & 7)) << 4));
}

// ---------------------------------------------------------------------------
// prep_kernel: block 0 = token dtype detect; blocks 1.. flat work list:
//   init(65536) | P=cnn@Win fp32 (65536) | W*0x(3x262144) | Wout(2560000) |
//   W*h n-major (3x131072) | W*1 n-major (3x262144)     total 4657152 items
// ---------------------------------------------------------------------------
__global__ void prep_kernel(const long long* __restrict__ t64,
    const float* __restrict__ cnn, const float* __restrict__ Win,
    const float* __restrict__ Wout,
    const float* __restrict__ Wu0, const float* __restrict__ Wr0,
    const float* __restrict__ Wc0,
    const float* __restrict__ Wu1, const float* __restrict__ Wr1,
    const float* __restrict__ Wc1)
{
    const int tid = threadIdx.x;
    if (blockIdx.x == 0) {
        __shared__ int bad;
        if (tid == 0) bad = 0;
        __syncthreads();
        for (int i = tid; i < cTB / 2; i += 256) {
            long long v = t64[i];
            if (v < 0 || v >= (long long)cV) bad = 1;
        }
        __syncthreads();
        if (tid == 0) d_tok64 = (bad == 0) ? 1 : 0;
        return;
    }
    long long idx = (long long)(blockIdx.x - 1) * 256 + tid;
    if (idx < 65536) {                      // init h (NOT d_P: written by P seg)
        int i = (int)idx;
        d_h0f[i] = 0.f; d_h1f[i] = 0.f;
        if (i < 32768) {
            d_h0pH[i] = 0u; d_h0pL[i] = 0u;
            d_h1pH[i] = 0u; d_h1pL[i] = 0u;
        }
        return;
    }
    idx -= 65536;
    if (idx < 65536) {                      // P[m][n] = cnn[m,:] @ Win[:,n] fp32
        int m = (int)(idx >> 9), n = (int)(idx & 511);
        const float* a = cnn + (long long)m * 2048;
        float s = 0.f;
        for (int k = 0; k < 2048; k += 4) {
            float4 av = *(const float4*)(a + k);
            s += av.x * Win[(long long)k * 512 + n];
            s += av.y * Win[(long long)(k + 1) * 512 + n];
            s += av.z * Win[(long long)(k + 2) * 512 + n];
            s += av.w * Win[(long long)(k + 3) * 512 + n];
        }
        d_P[idx] = s;
        return;
    }
    idx -= 65536;
    if (idx < 786432) {                     // Wu0x/Wr0x/Wc0x k-major [512][512]
        int w = (int)(idx >> 18);
        long long r = idx & 262143;
        const float* s = (w == 0) ? Wu0 : ((w == 1) ? Wr0 : (Wc0 + 512 * 512));
        uint32_t* oh = (w == 0) ? d_Wu0xH : ((w == 1) ? d_Wr0xH : d_Wc0xH);
        uint32_t* ol = (w == 0) ? d_Wu0xL : ((w == 1) ? d_Wr0xL : d_Wc0xL);
        int kp = (int)(r >> 9), n = (int)(r & 511);
        uint32_t h, l;
        bf16_split(s[(2 * kp) * 512 + n], s[(2 * kp + 1) * 512 + n], h, l);
        oh[r] = h; ol[r] = l;
        return;
    }
    idx -= 786432;
    if (idx < 2560000) {                    // Wout k-major [256][10000]
        int kp = (int)(idx / 10000);
        int n = (int)(idx - (long long)kp * 10000);
        uint32_t h, l;
        bf16_split(Wout[(long long)(2 * kp) * 10000 + n],
                   Wout[(long long)(2 * kp + 1) * 10000 + n], h, l);
        d_WoutH[idx] = h; d_WoutL[idx] = l;
        return;
    }
    idx -= 2560000;
    if (idx < 393216) {                     // WU0h/WR0h/WC0rh n-major [512][256]
        int w = (int)(idx >> 17);
        long long r = idx & 131071;
        const float* s = (w == 0) ? (Wu0 + 1024 * 512) : ((w == 1) ? (Wr0 + 1024 * 512) : Wc0);
        uint32_t* oh = (w == 0) ? d_WU0hH : ((w == 1) ? d_WR0hH : d_WC0rhH);
        uint32_t* ol = (w == 0) ? d_WU0hL : ((w == 1) ? d_WR0hL : d_WC0rhL);
        int n = (int)(r >> 8), kp = (int)(r & 255);
        uint32_t h, l;
        bf16_split(s[(2 * kp) * 512 + n], s[(2 * kp + 1) * 512 + n], h, l);
        oh[r] = h; ol[r] = l;
        return;
    }
    idx -= 393216;
    if (idx < 786432) {                     // WU1/WR1/WC1 n-major [512][512]
        int w = (int)(idx >> 18);
        long long r = idx & 262143;
        const float* s = (w == 0) ? Wu1 : ((w == 1) ? Wr1 : Wc1);
        uint32_t* oh = (w == 0) ? d_WU1H : ((w == 1) ? d_WR1H : d_WC1H);
        uint32_t* ol = (w == 0) ? d_WU1L : ((w == 1) ? d_WR1L : d_WC1L);
        int n = (int)(r >> 9), kp = (int)(r & 511);
        uint32_t h, l;
        bf16_split(s[(2 * kp) * 512 + n], s[(2 * kp + 1) * 512 + n], h, l);
        oh[r] = h; ol[r] = l;
    }
}

__global__ void gather_pack_kernel(const long long* __restrict__ tok64,
                                   const int* __restrict__ tok32,
                                   const float* __restrict__ emb,
                                   const float* __restrict__ bin_) {
    int idx = blockIdx.x * blockDim.x + threadIdx.x;
    if (idx >= cTB * 512) return;
    int m = idx >> 9, kp = idx & 511;
    int tt = m / cB, b = m % cB;
    float2 v;
    if (kp < 256) {
        int tok = d_tok64 ? (int)tok64[b * cT + tt] : tok32[b * cT + tt];
        v = *(const float2*)(emb + (long long)tok * cE + 2 * kp);
    } else {
        int k2 = kp - 256;
        float2 raw = *(const float2*)(d_P + b * cMAP + 2 * k2);
        v.x = raw.x + bin_[2 * k2];
        v.y = raw.y + bin_[2 * k2 + 1];
        v.x = v.x > 0.f ? v.x : 0.01f * v.x;
        v.y = v.y > 0.f ? v.y : 0.01f * v.y;
    }
    uint32_t h, l;
    bf16_split(v.x, v.y, h, l);
    d_XH[idx] = h; d_XL[idx] = l;
}

// ---------------------------------------------------------------------------
// gemm_core (ldmatrix edition). Pool per buffer (16KB):
//   [0,4K) A-hi  [4K,8K) A-lo  [8K,12K) B-hi  [12K,16K) B-lo
// 128 rows x 32B per operand, xor-swizzled. Double buffered: 32KB.
// ---------------------------------------------------------------------------
__device__ __forceinline__ void gemm_core(
    const uint32_t* __restrict__ AH, const uint32_t* __restrict__ AL, int as,
    const uint32_t* __restrict__ BH, const uint32_t* __restrict__ BL,
    const float* __restrict__ bias, float* __restrict__ C,
    int N, int K, int act, int remap, int m0, int n0, char* pool)
{
    const uint32_t sbase = smem_u32(pool);
    const int tid = threadIdx.x;
    const int wid = tid >> 5, lane = tid & 31;
    const int grp = lane >> 2, tig = lane & 3;
    const int wm = (wid >> 1) * 32, wn = (wid & 1) * 64;
    const int ar = tid >> 2, kb = (tid & 3) << 1;
    const int kp = (tid >> 4) & 7;
    const int bn = ((tid & 15) << 2) + ((tid >> 7) << 6);
    const int NC = K >> 4;

    const uint32_t oA0 = sw_off(ar, kb >> 2) + ((kb & 3) << 2);
    const uint32_t oA1 = sw_off(ar + 64, kb >> 2) + ((kb & 3) << 2);
    uint32_t oB[4];
#pragma unroll
    for (int j = 0; j < 4; j++) oB[j] = sw_off(bn + j, kp >> 2) + ((kp & 3) << 2);

    const int rA = (lane & 15);
    const uint32_t hA = (uint32_t)(lane >> 4);
    const int rB = (lane & 7) + ((lane >> 4) << 3);
    const uint32_t hB = (uint32_t)((lane >> 3) & 1);

    float acc[2][8][4] = {};
    uint2 a0h, a0l, a1h, a1l;
    uint4 bh, bl;

    {
        const uint32_t* pa = AH + (long long)(m0 + ar) * as + kb;
        const uint32_t* pl = AL + (long long)(m0 + ar) * as + kb;
        a0h = *(const uint2*)pa; a1h = *(const uint2*)(pa + (long long)64 * as);
        a0l = *(const uint2*)pl; a1l = *(const uint2*)(pl + (long long)64 * as);
        int n = n0 + bn;
        if (n < N) {
            bh = *(const uint4*)(BH + (long long)kp * N + n);
            bl = *(const uint4*)(BL + (long long)kp * N + n);
        } else { bh = make_uint4(0, 0, 0, 0); bl = bh; }
    }
    {
        char* pA = pool;
        char* pB = pool + 8192;
        *(uint2*)(pA + oA0) = a0h; *(uint2*)(pA + oA1) = a1h;
        *(uint2*)(pA + 4096 + oA0) = a0l; *(uint2*)(pA + 4096 + oA1) = a1l;
        *(uint32_t*)(pB + oB[0]) = bh.x; *(uint32_t*)(pB + oB[1]) = bh.y;
        *(uint32_t*)(pB + oB[2]) = bh.z; *(uint32_t*)(pB + oB[3]) = bh.w;
        *(uint32_t*)(pB + 4096 + oB[0]) = bl.x; *(uint32_t*)(pB + 4096 + oB[1]) = bl.y;
        *(uint32_t*)(pB + 4096 + oB[2]) = bl.z; *(uint32_t*)(pB + 4096 + oB[3]) = bl.w;
    }
    __syncthreads();

    for (int c = 0; c < NC; c++) {
        const int buf = c & 1;
        const int kn = (c + 1) << 4;
        if (kn < K) {
            const uint32_t* pa = AH + (long long)(m0 + ar) * as + (kn >> 1) + kb;
            const uint32_t* pl = AL + (long long)(m0 + ar) * as + (kn >> 1) + kb;
            a0h = *(const uint2*)pa; a1h = *(const uint2*)(pa + (long long)64 * as);
            a0l = *(const uint2*)pl; a1l = *(const uint2*)(pl + (long long)64 * as);
            int n = n0 + bn;
            if (n < N) {
                bh = *(const uint4*)(BH + (long long)((kn >> 1) + kp) * N + n);
                bl = *(const uint4*)(BL + (long long)((kn >> 1) + kp) * N + n);
            } else { bh = make_uint4(0, 0, 0, 0); bl = bh; }
        }

        const uint32_t base = sbase + (uint32_t)buf * 16384;
        uint32_t aHf[2][4], aLf[2][4];
#pragma unroll
        for (int mf = 0; mf < 2; mf++) {
            uint32_t addr = base + sw_off(wm + mf * 16 + rA, hA);
            ldsm4(aHf[mf][0], aHf[mf][1], aHf[mf][2], aHf[mf][3], addr);
            ldsm4(aLf[mf][0], aLf[mf][1], aLf[mf][2], aLf[mf][3], addr + 4096);
        }
#pragma unroll
        for (int nfp = 0; nfp < 4; nfp++) {
            uint32_t addrB = base + 8192 + sw_off(wn + nfp * 16 + rB, hB);
            uint32_t bH0, bH1, bH2, bH3, bL0, bL1, bL2, bL3;
            ldsm4(bH0, bH1, bH2, bH3, addrB);
            ldsm4(bL0, bL1, bL2, bL3, addrB + 4096);
#pragma unroll
            for (int mf = 0; mf < 2; mf++) {
                float* c0 = acc[mf][nfp * 2];
                float* c1 = acc[mf][nfp * 2 + 1];
                mma_bf(c0[0], c0[1], c0[2], c0[3],
                       aHf[mf][0], aHf[mf][1], aHf[mf][2], aHf[mf][3], bH0, bH1);
                mma_bf(c0[0], c0[1], c0[2], c0[3],
                       aHf[mf][0], aHf[mf][1], aHf[mf][2], aHf[mf][3], bL0, bL1);
                mma_bf(c0[0], c0[1], c0[2], c0[3],
                       aLf[mf][0], aLf[mf][1], aLf[mf][2], aLf[mf][3], bH0, bH1);
                mma_bf(c1[0], c1[1], c1[2], c1[3],
                       aHf[mf][0], aHf[mf][1], aHf[mf][2], aHf[mf][3], bH2, bH3);
                mma_bf(c1[0], c1[1], c1[2], c1[3],
                       aHf[mf][0], aHf[mf][1], aHf[mf][2], aHf[mf][3], bL2, bL3);
                mma_bf(c1[0], c1[1], c1[2], c1[3],
                       aLf[mf][0], aLf[mf][1], aLf[mf][2], aLf[mf][3], bH2, bH3);
            }
        }

        if (kn < K) {
            char* pA = pool + (buf ^ 1) * 16384;
            char* pB = pA + 8192;
            *(uint2*)(pA + oA0) = a0h; *(uint2*)(pA + oA1) = a1h;
            *(uint2*)(pA + 4096 + oA0) = a0l; *(uint2*)(pA + 4096 + oA1) = a1l;
            *(uint32_t*)(pB + oB[0]) = bh.x; *(uint32_t*)(pB + oB[1]) = bh.y;
            *(uint32_t*)(pB + oB[2]) = bh.z; *(uint32_t*)(pB + oB[3]) = bh.w;
            *(uint32_t*)(pB + 4096 + oB[0]) = bl.x; *(uint32_t*)(pB + 4096 + oB[1]) = bl.y;
            *(uint32_t*)(pB + 4096 + oB[2]) = bl.z; *(uint32_t*)(pB + 4096 + oB[3]) = bl.w;
        }
        __syncthreads();
    }

#pragma unroll
    for (int mf = 0; mf < 2; mf++) {
        int r0 = m0 + wm + mf * 16 + grp;
        int r1 = r0 + 8;
        long long base0, base1;
        if (remap) {
            int b0r = r0 & (cB - 1), t0 = r0 >> 7;
            int b1r = r1 & (cB - 1), t1 = r1 >> 7;
            base0 = (long long)(b0r * cT + t0) * N;
            base1 = (long long)(b1r * cT + t1) * N;
        } else {
            base0 = (long long)r0 * N;
            base1 = (long long)r1 * N;
        }
#pragma unroll
        for (int nf = 0; nf < 8; nf++) {
            int n = n0 + wn + nf * 8 + tig * 2;
            if (n < N) {
                float o00 = acc[mf][nf][0] + bias[n];
                float o01 = acc[mf][nf][1] + bias[n + 1];
                float o10 = acc[mf][nf][2] + bias[n];
                float o11 = acc[mf][nf][3] + bias[n + 1];
                if (act == 1) {
                    o00 = o00 > 0.f ? o00 : 0.01f * o00;
                    o01 = o01 > 0.f ? o01 : 0.01f * o01;
                    o10 = o10 > 0.f ? o10 : 0.01f * o10;
                    o11 = o11 > 0.f ? o11 : 0.01f * o11;
                }
                C[base0 + n] = o00; C[base0 + n + 1] = o01;
                C[base1 + n] = o10; C[base1 + n + 1] = o11;
            }
        }
    }
}

// wrappers -------------------------------------------------------------------
__global__ __launch_bounds__(256) void pre3_gemm(
    const float* __restrict__ bu0, const float* __restrict__ br0,
    const float* __restrict__ bc0) {
    __shared__ __align__(16) char pool[32768];
    int z = blockIdx.z;
    const uint32_t* BH = (z == 0) ? d_Wu0xH : ((z == 1) ? d_Wr0xH : d_Wc0xH);
    const uint32_t* BL = (z == 0) ? d_Wu0xL : ((z == 1) ? d_Wr0xL : d_Wc0xL);
    const float* bias = (z == 0) ? bu0 : ((z == 1) ? br0 : bc0);
    float* C = (z == 0) ? d_A0u : ((z == 1) ? d_A0r : d_A0c);
    gemm_core(d_XH, d_XL, 512, BH, BL, bias, C, 512, 1024, 0, 0,
              blockIdx.y * 128, blockIdx.x * 128, pool);
}

__global__ __launch_bounds__(256) void logits_gemm(
    const float* __restrict__ bout, float* __restrict__ out) {
    __shared__ __align__(16) char pool[32768];
    gemm_core(d_H1H, d_H1L, 256, d_WoutH, d_WoutL, bout, out, cV, 512, 0, 1,
              blockIdx.y * 128, blockIdx.x * 128, pool);
}

// ---------------------------------------------------------------------------
// Persistent recurrent loop. tile_gemm uses an explicit 2-stage register
// double-buffer: live loads bounded to 2 iterations (~64 regs) -> no spills.
// ---------------------------------------------------------------------------
__device__ __forceinline__ void grid_bar() {
    __syncthreads();
    if (threadIdx.x == 0) {
        unsigned gen = g_gen;
        __threadfence();
        if (atomicAdd(&g_cnt, 1u) == 127u) {
            atomicExch(&g_cnt, 0u);
            __threadfence();
            g_gen = gen + 1;
        } else {
            while (g_gen == gen) { }
        }
        __threadfence();
    }
    __syncthreads();
}

template <int NITER, int MF>
__device__ __forceinline__ void tile_gemm(
    const uint32_t* __restrict__ AH, const uint32_t* __restrict__ AL, int kpa0,
    const uint32_t* __restrict__ BH, const uint32_t* __restrict__ BL, int bs, int kpb0,
    int m0, int n0, int grp, int tig, float (&acc)[MF][4][4])
{
    uint32_t aHx[2][MF][4], aLx[2][MF][4];
    uint32_t bHx[2][4][2], bLx[2][4][2];

    auto load_iter = [&](int it, int sb) {
        const int kpA = kpa0 + it * 8, kpB = kpb0 + it * 8;
#pragma unroll
        for (int mf = 0; mf < MF; mf++) {
            const int r = (m0 + mf * 16 + grp) * 256 + kpA;
            aHx[sb][mf][0] = __ldcg(AH + r + tig);
            aHx[sb][mf][1] = __ldcg(AH + r + 2048 + tig);
            aHx[sb][mf][2] = __ldcg(AH + r + tig + 4);
            aHx[sb][mf][3] = __ldcg(AH + r + 2048 + tig + 4);
            aLx[sb][mf][0] = __ldcg(AL + r + tig);
            aLx[sb][mf][1] = __ldcg(AL + r + 2048 + tig);
            aLx[sb][mf][2] = __ldcg(AL + r + tig + 4);
            aLx[sb][mf][3] = __ldcg(AL + r + 2048 + tig + 4);
        }
#pragma unroll
        for (int nf = 0; nf < 4; nf++) {
            const int nb = (n0 + nf * 8 + grp) * bs + kpB;
            bHx[sb][nf][0] = __ldg(BH + nb + tig);
            bHx[sb][nf][1] = __ldg(BH + nb + tig + 4);
            bLx[sb][nf][0] = __ldg(BL + nb + tig);
            bLx[sb][nf][1] = __ldg(BL + nb + tig + 4);
        }
    };

    load_iter(0, 0);
#pragma unroll
    for (int it = 0; it < NITER; it++) {
        const int sb = it & 1;
        if (it + 1 < NITER) load_iter(it + 1, sb ^ 1);
#pragma unroll
        for (int nf = 0; nf < 4; nf++) {
            uint32_t b0H = bHx[sb][nf][0], b1H = bHx[sb][nf][1];
            uint32_t b0L = bLx[sb][nf][0], b1L = bLx[sb][nf][1];
#pragma unroll
            for (int mf = 0; mf < MF; mf++) {
                float* c = acc[mf][nf];
                mma_bf(c[0], c[1], c[2], c[3],
                       aHx[sb][mf][0], aHx[sb][mf][1], aHx[sb][mf][2], aHx[sb][mf][3],
                       b0H, b1H);
                mma_bf(c[0], c[1], c[2], c[3],
                       aHx[sb][mf][0], aHx[sb][mf][1], aHx[sb][mf][2], aHx[sb][mf][3],
                       b0L, b1L);
                mma_bf(c[0], c[1], c[2], c[3],
                       aLx[sb][mf][0], aLx[sb][mf][1], aLx[sb][mf][2], aLx[sb][mf][3],
                       b0H, b1H);
            }
        }
    }
}

template <int MF>
__device__ __forceinline__ void store_red(float (*red)[1024], float (&acc)[MF][4][4],
                                          int wid, int grp, int tig) {
#pragma unroll
    for (int mf = 0; mf < MF; mf++)
#pragma unroll
        for (int nf = 0; nf < 4; nf++) {
            int c = nf * 8 + tig * 2, r = mf * 16 + grp;
            red[wid][r * 32 + c] = acc[mf][nf][0];
            red[wid][r * 32 + c + 1] = acc[mf][nf][1];
            red[wid][(r + 8) * 32 + c] = acc[mf][nf][2];
            red[wid][(r + 8) * 32 + c + 1] = acc[mf][nf][3];
        }
}

__device__ __forceinline__ float4 sum_red4(float (*red)[1024], int e0) {
    float4 s = make_float4(0, 0, 0, 0);
#pragma unroll
    for (int w = 0; w < 8; w++) {
        float4 r = *(float4*)&red[w][e0];
        s.x += r.x; s.y += r.y; s.z += r.z; s.w += r.w;
    }
    return s;
}

__device__ __forceinline__ float2 sum_red2(float (*red)[1024], int e0) {
    float2 s = make_float2(0, 0);
#pragma unroll
    for (int w = 0; w < 8; w++) {
        float2 r = *(float2*)&red[w][e0];
        s.x += r.x; s.y += r.y;
    }
    return s;
}

__global__ __launch_bounds__(256) void loop_kernel(
    const float* __restrict__ bu1, const float* __restrict__ br1,
    const float* __restrict__ bc1)
{
    __shared__ float red[8][1024];
    const int tid = threadIdx.x, wid = tid >> 5, lane = tid & 31;
    const int grp = lane >> 2, tig = lane & 3;
    const int blk = blockIdx.x;

    for (int t = 0; t < cT; t++) {
        // ---- phase A: u0 (blk<64) / r0 (blk>=64), 32x32 tiles, K=512 ----
        {
            int gate = blk >> 6, tile = blk & 63;
            int m0 = (tile & 3) * 32, n0 = (tile >> 2) * 32;
            float acc[2][4][4] = {};
            tile_gemm<4, 2>(d_h0pH, d_h0pL, wid * 32,
                            gate ? d_WR0hH : d_WU0hH, gate ? d_WR0hL : d_WU0hL,
                            256, wid * 32, m0, n0, grp, tig, acc);
            store_red<2>(red, acc, wid, grp, tig);
            __syncthreads();
            const float* A0 = (gate ? d_A0r : d_A0u) + t * cB * cH;
            int e0 = tid * 4;
            float4 s = sum_red4(red, e0);
            int m = m0 + (e0 >> 5), n = n0 + (e0 & 31), o = m * cH + n;
            float4 a = *(const float4*)(A0 + o);
            if (gate == 0) {
                d_U0[o] = sigf(a.x + s.x);     d_U0[o + 1] = sigf(a.y + s.y);
                d_U0[o + 2] = sigf(a.z + s.z); d_U0[o + 3] = sigf(a.w + s.w);
            } else {
                float r0 = sigf(a.x + s.x) * __ldcg(d_h0f + o);
                float r1 = sigf(a.y + s.y) * __ldcg(d_h0f + o + 1);
                float r2 = sigf(a.z + s.z) * __ldcg(d_h0f + o + 2);
                float r3 = sigf(a.w + s.w) * __ldcg(d_h0f + o + 3);
                uint32_t h, l;
                int kp = m * 256 + (n >> 1);
                bf16_split(r0, r1, h, l); d_RH0H[kp] = h;     d_RH0L[kp] = l;
                bf16_split(r2, r3, h, l); d_RH0H[kp + 1] = h; d_RH0L[kp + 1] = l;
            }
        }
        grid_bar();
        // ---- phase B: c0, 16x32 tiles, K=512, in-place h0 update ----
        {
            int m0 = (blk & 7) * 16, n0 = (blk >> 3) * 32;
            float acc[1][4][4] = {};
            tile_gemm<4, 1>(d_RH0H, d_RH0L, wid * 32,
                            d_WC0rhH, d_WC0rhL, 256, wid * 32, m0, n0, grp, tig, acc);
            store_red<1>(red, acc, wid, grp, tig);
            __syncthreads();
            const float* A0 = d_A0c + t * cB * cH;
            int e0 = tid * 2;
            float2 s = sum_red2(red, e0);
            int m = m0 + (e0 >> 5), n = n0 + (e0 & 31), o = m * cH + n;
            float v0 = A0[o] + s.x, v1 = A0[o + 1] + s.y;
            float u0 = __ldcg(d_U0 + o), u1 = __ldcg(d_U0 + o + 1);
            float p0 = __ldcg(d_h0f + o), p1 = __ldcg(d_h0f + o + 1);
            float n0v = u0 * p0 + (1.f - u0) * tanhf(v0);
            float n1v = u1 * p1 + (1.f - u1) * tanhf(v1);
            d_h0f[o] = n0v; d_h0f[o + 1] = n1v;
            uint32_t h, l;
            bf16_split(n0v, n1v, h, l);
            int kp = m * 256 + (n >> 1);
            d_h0pH[kp] = h; d_h0pL[kp] = l;
        }
        grid_bar();
        // ---- phase C: u1 / r1, 32x32 tiles, K=1024 ([h0,h1]) ----
        {
            int gate = blk >> 6, tile = blk & 63;
            int m0 = (tile & 3) * 32, n0 = (tile >> 2) * 32;
            float acc[2][4][4] = {};
            tile_gemm<8, 2>((wid < 4) ? d_h0pH : d_h1pH, (wid < 4) ? d_h0pL : d_h1pL,
                            (wid & 3) * 64,
                            gate ? d_WR1H : d_WU1H, gate ? d_WR1L : d_WU1L,
                            512, wid * 64, m0, n0, grp, tig, acc);
            store_red<2>(red, acc, wid, grp, tig);
            __syncthreads();
            const float* bb = gate ? br1 : bu1;
            int e0 = tid * 4;
            float4 s = sum_red4(red, e0);
            int m = m0 + (e0 >> 5), n = n0 + (e0 & 31), o = m * cH + n;
            float4 b = *(const float4*)(bb + n);
            if (gate == 0) {
                d_U1[o] = sigf(b.x + s.x);     d_U1[o + 1] = sigf(b.y + s.y);
                d_U1[o + 2] = sigf(b.z + s.z); d_U1[o + 3] = sigf(b.w + s.w);
            } else {
                float r0 = sigf(b.x + s.x) * __ldcg(d_h1f + o);
                float r1 = sigf(b.y + s.y) * __ldcg(d_h1f + o + 1);
                float r2 = sigf(b.z + s.z) * __ldcg(d_h1f + o + 2);
                float r3 = sigf(b.w + s.w) * __ldcg(d_h1f + o + 3);
                uint32_t h, l;
                int kp = m * 256 + (n >> 1);
                bf16_split(r0, r1, h, l); d_RH1H[kp] = h;     d_RH1L[kp] = l;
                bf16_split(r2, r3, h, l); d_RH1H[kp + 1] = h; d_RH1L[kp + 1] = l;
            }
        }
        grid_bar();
        // ---- phase D: c1, 16x32 tiles, K=1024 ([RH1,h0]); no barrier after ----
        {
            int m0 = (blk & 7) * 16, n0 = (blk >> 3) * 32;
            float acc[1][4][4] = {};
            tile_gemm<8, 1>((wid < 4) ? d_RH1H : d_h0pH, (wid < 4) ? d_RH1L : d_h0pL,
                            (wid & 3) * 64,
                            d_WC1H, d_WC1L, 512, wid * 64, m0, n0, grp, tig, acc);
            store_red<1>(red, acc, wid, grp, tig);
            __syncthreads();
            int e0 = tid * 2;
            float2 s = sum_red2(red, e0);
            int m = m0 + (e0 >> 5), n = n0 + (e0 & 31), o = m * cH + n;
            float v0 = bc1[n] + s.x, v1 = bc1[n + 1] + s.y;
            float u0 = __ldcg(d_U1 + o), u1 = __ldcg(d_U1 + o + 1);
            float p0 = __ldcg(d_h1f + o), p1 = __ldcg(d_h1f + o + 1);
            float n0v = u0 * p0 + (1.f - u0) * tanhf(v0);
            float n1v = u1 * p1 + (1.f - u1) * tanhf(v1);
            d_h1f[o] = n0v; d_h1f[o + 1] = n1v;
            uint32_t h, l;
            bf16_split(n0v, n1v, h, l);
            int kp = m * 256 + (n >> 1);
            d_h1pH[kp] = h; d_h1pL[kp] = l;
            long long hp = (long long)(t * cB + m) * 256 + (n >> 1);
            d_H1H[hp] = h; d_H1L[hp] = l;
            __syncthreads();
        }
    }
}

__global__ void hidden_out_kernel(float* __restrict__ out) {
    int i = blockIdx.x * blockDim.x + threadIdx.x;
    if (i < cB * cH) {
        out[LOGITS_ELEMS + i] = d_h0f[i];
        out[LOGITS_ELEMS + cB * cH + i] = d_h1f[i];
    }
}

// ---------------------------------------------------------------------------
extern "C" void kernel_launch(void* const* d_in, const int* in_sizes, int n_in,
                              void* d_out, int out_size) {
    const long long* tok64 = (const long long*)d_in[0];
    const int*       tok32 = (const int*)d_in[0];
    const float* cnn  = (const float*)d_in[1];
    const float* emb  = (const float*)d_in[2];
    const float* Win  = (const float*)d_in[3];
    const float* bin_ = (const float*)d_in[4];
    const float* Wout = (const float*)d_in[5];
    const float* bout = (const float*)d_in[6];
    const float* Wu0  = (const float*)d_in[7];
    const float* bu0  = (const float*)d_in[8];
    const float* Wr0  = (const float*)d_in[9];
    const float* br0  = (const float*)d_in[10];
    const float* Wc0  = (const float*)d_in[11];
    const float* bc0  = (const float*)d_in[12];
    const float* Wu1  = (const float*)d_in[13];
    const float* bu1  = (const float*)d_in[14];
    const float* Wr1  = (const float*)d_in[15];
    const float* br1  = (const float*)d_in[16];
    const float* Wc1  = (const float*)d_in[17];
    const float* bc1  = (const float*)d_in[18];
    float* out = (float*)d_out;

    // launch 0: fused prep (detect + init + fp32 P + all packing)
    prep_kernel<<<18193, 256>>>(tok64, cnn, Win, Wout, Wu0, Wr0, Wc0, Wu1, Wr1, Wc1);
    // launch 1: gather + bias/leaky on P + pack X
    gather_pack_kernel<<<(cTB * 512 + 255) / 256, 256>>>(tok64, tok32, emb, bin_);
    // launch 2: precompute A0u/A0r/A0c = X @ Wx + b (ldmatrix engine)
    pre3_gemm<<<dim3(4, 25, 3), 256>>>(bu0, br0, bc0);
    // launch 3 (ncu-profiled): persistent recurrent loop (all 25 steps)
    loop_kernel<<<128, 256>>>(bu1, br1, bc1);
    // launch 4: logits = H1 @ Wout + bout -> [B,T,V]
    logits_gemm<<<dim3((cV + 127) / 128, 25), 256>>>(bout, out);
    // launch 5: hidden state outputs
    hidden_out_kernel<<<(cB * cH + 255) / 256, 256>>>(out);
}